// round 16
// baseline (speedup 1.0000x reference)
// MoE top-2, grouped-GEMM formulation for GB300 (sm_103a).
// Round 15: int8 3-term split GEMMs on mma.sync.m16n8k32.s8 (exact s32 accum).
//           Measured law: time = 675us x (MMA k16-equivalents) + 450us.
//           fp16 2-term = 2.0 equiv -> int8 3-term@k32 = 1.5 equiv.
//           Per-row scales (exact) for x/w; hmid requantized with fixed
//           saturating scale S_H=5/16256. BK=64 (half the barriers).
//           Warp tile 32x32, 16 warps, 512 thr, dual s32 acc sets (~120 regs).
//   kQ: per-row quantize x / w_fc / w_proj to s8 hi/lo planes (+zero out,counts)
//   k1: router (unchanged)   k2: scan (unchanged)
//   k3: grouped GEMM1  hmid = gelu(x @ w_fc^T + b_fc)  -> s8 hi/lo + S_H
//   k4: grouped GEMM2  out += gate * (hmid @ w_proj^T + b_proj)  [atomicAdd]
#include <cuda_runtime.h>
#include <cstdint>

#define DEVFN __device__ __forceinline__

constexpr int H_ = 1024;
constexpr int I_ = 2048;
constexpr int E_ = 8;
constexpr int T_ = 16384;
constexpr int NPAIR = 2 * T_;

constexpr int BM = 128, BN = 128, BK = 64;
constexpr int PBB = 80;                  // bytes per smem row (64 data + 16 pad)
constexpr int PLANE = BM * PBB;          // 10240 B
constexpr int STAGE = 4 * PLANE;         // Ahi, Alo, Bhi, Blo = 40960 B
constexpr int SMEM_TOTAL = 2 * STAGE;    // 81920 B

constexpr float QMAX   = 16256.0f;       // 127*128
constexpr float S_H    = 5.0f / 16256.0f;
constexpr float INV_SH = 16256.0f / 5.0f;

// ---------------- scratch (device globals; no runtime allocation) ----------------
__device__ int   g_counts[E_];
__device__ int   g_offsets[E_];
__device__ int   g_tok[E_ * T_];
__device__ float g_gate[E_ * T_];

__device__ float g_sx[T_];          // per-token scale of x
__device__ float g_sfc[E_ * I_];    // per-channel scale of w_fc rows
__device__ float g_spj[E_ * H_];    // per-channel scale of w_proj rows

__device__ int8_t g_xhi[(size_t)T_ * H_],      g_xlo[(size_t)T_ * H_];
__device__ int8_t g_fchi[(size_t)E_ * I_ * H_], g_fclo[(size_t)E_ * I_ * H_];
__device__ int8_t g_pjhi[(size_t)E_ * H_ * I_], g_pjlo[(size_t)E_ * H_ * I_];
__device__ int8_t g_hmhi[(size_t)NPAIR * I_],  g_hmlo[(size_t)NPAIR * I_];

// ---------------- helpers ----------------
DEVFN void cp_async16(uint32_t smem_addr, const void* gptr) {
    asm volatile("cp.async.cg.shared.global [%0], [%1], 16;\n"
                 :: "r"(smem_addr), "l"(gptr));
}
DEVFN void cp_commit() { asm volatile("cp.async.commit_group;\n"); }
template <int N> DEVFN void cp_wait() {
    asm volatile("cp.async.wait_group %0;\n" :: "n"(N));
}

DEVFN void mma_s8(int c[4], const uint32_t a[4], uint32_t b0, uint32_t b1) {
    asm volatile(
        "mma.sync.aligned.m16n8k32.row.col.s32.s8.s8.s32 "
        "{%0,%1,%2,%3}, {%4,%5,%6,%7}, {%8,%9}, {%0,%1,%2,%3};\n"
        : "+r"(c[0]), "+r"(c[1]), "+r"(c[2]), "+r"(c[3])
        : "r"(a[0]), "r"(a[1]), "r"(a[2]), "r"(a[3]), "r"(b0), "r"(b1));
}

DEVFN float gelu_f(float v) {
    return 0.5f * v * (1.0f + erff(v * 0.70710678118654752440f));
}

// quantize one float with clamp; q = v*inv in [-QMAX,QMAX]; v ~= s*(128*h + l)
DEVFN void quant1(float v, float inv, int& h, int& l) {
    float q = fminf(fmaxf(v * inv, -QMAX), QMAX);
    h = __float2int_rn(q * 0.0078125f);          // /128, |h| <= 127
    l = __float2int_rn(q - 128.0f * (float)h);   // |l| <= 64
}

// ---------------- kQ: per-row quantization (+ zero out, counts) ----------------
__global__ void quant_all_kernel(const float4* __restrict__ x,
                                 const float4* __restrict__ wfc,
                                 const float4* __restrict__ wproj,
                                 float4* __restrict__ out) {
    const int b = blockIdx.x, tid = threadIdx.x;
    if (b == 0 && tid < E_) g_counts[tid] = 0;

    const float4* src; uint32_t* hi; uint32_t* lo; float* sdst;
    int len4; size_t row4; bool isx = false;
    if (b < T_) {
        src = x; hi = (uint32_t*)g_xhi; lo = (uint32_t*)g_xlo;
        sdst = g_sx + b; len4 = H_ / 4; row4 = (size_t)b * len4; isx = true;
    } else if (b < T_ + E_ * I_) {
        const int w = b - T_;
        src = wfc; hi = (uint32_t*)g_fchi; lo = (uint32_t*)g_fclo;
        sdst = g_sfc + w; len4 = H_ / 4; row4 = (size_t)w * len4;
    } else {
        const int w = b - T_ - E_ * I_;
        src = wproj; hi = (uint32_t*)g_pjhi; lo = (uint32_t*)g_pjlo;
        sdst = g_spj + w; len4 = I_ / 4; row4 = (size_t)w * len4;
    }

    float m = 0.f;
    for (int i = tid; i < len4; i += 128) {
        const float4 v = src[row4 + i];
        m = fmaxf(m, fmaxf(fmaxf(fabsf(v.x), fabsf(v.y)), fmaxf(fabsf(v.z), fabsf(v.w))));
        if (isx) out[row4 + i] = make_float4(0.f, 0.f, 0.f, 0.f);
    }
#pragma unroll
    for (int s = 16; s; s >>= 1) m = fmaxf(m, __shfl_xor_sync(0xffffffffu, m, s));
    __shared__ float wmax[4];
    const int warp = tid >> 5, lane = tid & 31;
    if (lane == 0) wmax[warp] = m;
    __syncthreads();
    m = fmaxf(fmaxf(wmax[0], wmax[1]), fmaxf(wmax[2], wmax[3]));
    m = fmaxf(m, 1e-30f);
    if (tid == 0) *sdst = m / QMAX;
    const float inv = QMAX / m;

    for (int i = tid; i < len4; i += 128) {
        const float4 v = src[row4 + i];
        const float vv[4] = {v.x, v.y, v.z, v.w};
        uint32_t hp = 0, lp = 0;
#pragma unroll
        for (int j = 0; j < 4; ++j) {
            int h, l;
            quant1(vv[j], inv, h, l);
            hp |= ((uint32_t)(uint8_t)(int8_t)h) << (8 * j);
            lp |= ((uint32_t)(uint8_t)(int8_t)l) << (8 * j);
        }
        hi[row4 + i] = hp;
        lo[row4 + i] = lp;
    }
}

// ---------------- k1: router (unchanged) ----------------
__global__ void route_kernel(const float* __restrict__ x,
                             const float* __restrict__ w_gate) {
    __shared__ float4 sWg[E_ * (H_ / 4)];   // 32 KB
    const int tid = threadIdx.x;
    for (int i = tid; i < E_ * (H_ / 4); i += 128)
        sWg[i] = ((const float4*)w_gate)[i];
    __syncthreads();

    const int t = blockIdx.x * 128 + tid;
    const float4* xr = (const float4*)(x + (size_t)t * H_);
    float acc[E_];
#pragma unroll
    for (int e = 0; e < E_; ++e) acc[e] = 0.f;

    for (int i = 0; i < H_ / 4; ++i) {
        const float4 v = xr[i];
#pragma unroll
        for (int e = 0; e < E_; ++e) {
            const float4 w = sWg[e * (H_ / 4) + i];
            acc[e] = fmaf(v.x, w.x, fmaf(v.y, w.y, fmaf(v.z, w.z, fmaf(v.w, w.w, acc[e]))));
        }
    }

    int e1 = 0; float v1 = acc[0];
#pragma unroll
    for (int e = 1; e < E_; ++e) if (acc[e] > v1) { v1 = acc[e]; e1 = e; }
    int e2 = -1; float v2 = -3.4e38f;
#pragma unroll
    for (int e = 0; e < E_; ++e) if (e != e1 && acc[e] > v2) { v2 = acc[e]; e2 = e; }

    const float d  = expf(v2 - v1);
    const float iv = 1.0f / (1.0f + d);
    const float g1 = iv, g2 = d * iv;

    int p1 = atomicAdd(&g_counts[e1], 1);
    g_tok[e1 * T_ + p1] = t;  g_gate[e1 * T_ + p1] = g1;
    int p2 = atomicAdd(&g_counts[e2], 1);
    g_tok[e2 * T_ + p2] = t;  g_gate[e2 * T_ + p2] = g2;
}

// ---------------- k2: exclusive scan ----------------
__global__ void scan_kernel() {
    int o = 0;
#pragma unroll
    for (int e = 0; e < E_; ++e) { g_offsets[e] = o; o += g_counts[e]; }
}

// ---------------- per-stage int8 compute: 16 warps as 4(M)x4(N), warp tile 32x32 ----------------
// m16n8k32.s8 fragments: a0=(row g, k 4tg..+3) a1=(g+8,same) a2=(g,+16) a3=(g+8,+16)
//                        b0=(col g, k 4tg..+3) b1=(col g, +16); C rows g/g+8, cols 2tg,2tg+1
DEVFN void compute_stage(const int8_t* __restrict__ base, int g, int tg, int wm, int wn,
                         int acc1[2][4][4], int acc23[2][4][4]) {
    const int8_t* Ah = base;
    const int8_t* Al = base + PLANE;
    const int8_t* Bh = base + 2 * PLANE;
    const int8_t* Bl = base + 3 * PLANE;
#pragma unroll
    for (int ks = 0; ks < 2; ++ks) {
        const int kb = ks * 32 + tg * 4;
        uint32_t ah[2][4], al[2][4];
#pragma unroll
        for (int mi = 0; mi < 2; ++mi) {
            const int o = (wm * 32 + mi * 16 + g) * PBB + kb;
            ah[mi][0] = *(const uint32_t*)(Ah + o);
            ah[mi][1] = *(const uint32_t*)(Ah + o + 8 * PBB);
            ah[mi][2] = *(const uint32_t*)(Ah + o + 16);
            ah[mi][3] = *(const uint32_t*)(Ah + o + 8 * PBB + 16);
            al[mi][0] = *(const uint32_t*)(Al + o);
            al[mi][1] = *(const uint32_t*)(Al + o + 8 * PBB);
            al[mi][2] = *(const uint32_t*)(Al + o + 16);
            al[mi][3] = *(const uint32_t*)(Al + o + 8 * PBB + 16);
        }
#pragma unroll
        for (int ni = 0; ni < 4; ++ni) {
            const int o = (wn * 32 + ni * 8 + g) * PBB + kb;
            const uint32_t bh0 = *(const uint32_t*)(Bh + o);
            const uint32_t bh1 = *(const uint32_t*)(Bh + o + 16);
            const uint32_t bl0 = *(const uint32_t*)(Bl + o);
            const uint32_t bl1 = *(const uint32_t*)(Bl + o + 16);
#pragma unroll
            for (int mi = 0; mi < 2; ++mi)    // qh*qh  (weight 16384)
                mma_s8(acc1[mi][ni], ah[mi], bh0, bh1);
#pragma unroll
            for (int mi = 0; mi < 2; ++mi)    // ql*qh  (weight 128)
                mma_s8(acc23[mi][ni], al[mi], bh0, bh1);
#pragma unroll
            for (int mi = 0; mi < 2; ++mi)    // qh*ql  (weight 128)
                mma_s8(acc23[mi][ni], ah[mi], bl0, bl1);
        }
    }
}

// stage loader: 512 threads, each does one 16B chunk of one row in each of 4 planes
DEVFN void load_stage(uint32_t smu, int stage,
                      const int8_t* aH, const int8_t* aL,
                      const int8_t* bH, const int8_t* bL,
                      int k0, int r, int cc) {
    const uint32_t sb = smu + (uint32_t)(stage * STAGE);
    const uint32_t so = (uint32_t)(r * PBB + cc * 16);
    cp_async16(sb + so,             aH + k0);
    cp_async16(sb + PLANE + so,     aL + k0);
    cp_async16(sb + 2 * PLANE + so, bH + k0);
    cp_async16(sb + 3 * PLANE + so, bL + k0);
}

// ---------------- k3: grouped GEMM1 (int8) ----------------
__global__ __launch_bounds__(512, 1)
void gemm_fc_kernel(const float* __restrict__ b_fc) {
    const int e    = blockIdx.z;
    const int tile = blockIdx.y;
    const int cnt  = g_counts[e];
    if (tile * BM >= cnt) return;
    const int rem  = min(cnt - tile * BM, BM);
    const int hoff = g_offsets[e];
    const int n0   = blockIdx.x * BN;

    extern __shared__ int8_t sm[];
    __shared__ int   tok_s[BM];
    __shared__ float sx_s[BM];

    const int tid = threadIdx.x;
    if (tid < BM) {
        const int tk = g_tok[e * T_ + min(tile * BM + tid, cnt - 1)];
        tok_s[tid] = tk;
        sx_s[tid]  = g_sx[tk];
    }
    __syncthreads();

    const int cc = tid & 3;          // 16B chunk within BK=64
    const int r  = tid >> 2;         // 0..127
    const int8_t* aH = g_xhi + (size_t)tok_s[r] * H_ + cc * 16;
    const int8_t* aL = g_xlo + (size_t)tok_s[r] * H_ + cc * 16;
    const int8_t* bH = g_fchi + ((size_t)e * I_ + n0 + r) * H_ + cc * 16;
    const int8_t* bL = g_fclo + ((size_t)e * I_ + n0 + r) * H_ + cc * 16;
    const uint32_t smu = (uint32_t)__cvta_generic_to_shared(sm);

    const int lane = tid & 31, warp = tid >> 5;
    const int g = lane >> 2, tg = lane & 3;
    const int wm = warp >> 2, wn = warp & 3;   // 4(M) x 4(N)

    int acc1[2][4][4], acc23[2][4][4];
#pragma unroll
    for (int mi = 0; mi < 2; ++mi)
#pragma unroll
        for (int ni = 0; ni < 4; ++ni)
#pragma unroll
            for (int q = 0; q < 4; ++q) { acc1[mi][ni][q] = 0; acc23[mi][ni][q] = 0; }

    constexpr int KT = H_ / BK;   // 16
    load_stage(smu, 0, aH, aL, bH, bL, 0, r, cc);
    cp_commit();
    for (int kt = 0; kt < KT; ++kt) {
        cp_wait<0>();
        __syncthreads();
        if (kt + 1 < KT) {
            load_stage(smu, (kt + 1) & 1, aH, aL, bH, bL, (kt + 1) * BK, r, cc);
            cp_commit();
        }
        compute_stage(sm + (size_t)(kt & 1) * STAGE, g, tg, wm, wn, acc1, acc23);
    }

    // epilogue: dequant, bias, gelu, requant to hmid planes (fixed S_H)
    const float* bf = b_fc + e * I_;
    const size_t base = (size_t)(hoff + tile * BM);
#pragma unroll
    for (int mi = 0; mi < 2; ++mi) {
        const int rr = wm * 32 + mi * 16 + g;
#pragma unroll
        for (int ni = 0; ni < 4; ++ni) {
            const int colg = n0 + wn * 32 + ni * 8 + 2 * tg;
            const float sc0 = __ldg(&g_sfc[e * I_ + colg]);
            const float sc1 = __ldg(&g_sfc[e * I_ + colg + 1]);
            if (rr < rem) {
                const float s = sx_s[rr];
                const float v0 = gelu_f((16384.f * (float)acc1[mi][ni][0] +
                                         128.f * (float)acc23[mi][ni][0]) * (s * sc0) + bf[colg]);
                const float v1 = gelu_f((16384.f * (float)acc1[mi][ni][1] +
                                         128.f * (float)acc23[mi][ni][1]) * (s * sc1) + bf[colg + 1]);
                int h0, l0, h1, l1;
                quant1(v0, INV_SH, h0, l0);
                quant1(v1, INV_SH, h1, l1);
                const size_t o = (base + rr) * I_ + colg;
                *(uint16_t*)(g_hmhi + o) = (uint16_t)((uint8_t)(int8_t)h0 | ((uint16_t)(uint8_t)(int8_t)h1 << 8));
                *(uint16_t*)(g_hmlo + o) = (uint16_t)((uint8_t)(int8_t)l0 | ((uint16_t)(uint8_t)(int8_t)l1 << 8));
            }
            if (rr + 8 < rem) {
                const float s = sx_s[rr + 8];
                const float v0 = gelu_f((16384.f * (float)acc1[mi][ni][2] +
                                         128.f * (float)acc23[mi][ni][2]) * (s * sc0) + bf[colg]);
                const float v1 = gelu_f((16384.f * (float)acc1[mi][ni][3] +
                                         128.f * (float)acc23[mi][ni][3]) * (s * sc1) + bf[colg + 1]);
                int h0, l0, h1, l1;
                quant1(v0, INV_SH, h0, l0);
                quant1(v1, INV_SH, h1, l1);
                const size_t o = (base + rr + 8) * I_ + colg;
                *(uint16_t*)(g_hmhi + o) = (uint16_t)((uint8_t)(int8_t)h0 | ((uint16_t)(uint8_t)(int8_t)h1 << 8));
                *(uint16_t*)(g_hmlo + o) = (uint16_t)((uint8_t)(int8_t)l0 | ((uint16_t)(uint8_t)(int8_t)l1 << 8));
            }
        }
    }
}

// ---------------- k4: grouped GEMM2 (int8) ----------------
__global__ __launch_bounds__(512, 1)
void gemm_proj_kernel(const float* __restrict__ b_proj, float* __restrict__ out) {
    const int e    = blockIdx.z;
    const int tile = blockIdx.y;
    const int cnt  = g_counts[e];
    if (tile * BM >= cnt) return;
    const int rem  = min(cnt - tile * BM, BM);
    const int hoff = g_offsets[e];
    const int n0   = blockIdx.x * BN;

    extern __shared__ int8_t sm[];
    __shared__ int   tok_s[BM];
    __shared__ float gate_s[BM];

    const int tid = threadIdx.x;
    if (tid < BM) {
        const int idx = e * T_ + min(tile * BM + tid, cnt - 1);
        tok_s[tid]  = g_tok[idx];
        gate_s[tid] = g_gate[idx];
    }
    __syncthreads();

    const int cc = tid & 3;
    const int r  = tid >> 2;
    const int slot = min(hoff + tile * BM + r, NPAIR - 1);
    const int8_t* aH = g_hmhi + (size_t)slot * I_ + cc * 16;
    const int8_t* aL = g_hmlo + (size_t)slot * I_ + cc * 16;
    const int8_t* bH = g_pjhi + ((size_t)e * H_ + n0 + r) * I_ + cc * 16;
    const int8_t* bL = g_pjlo + ((size_t)e * H_ + n0 + r) * I_ + cc * 16;
    const uint32_t smu = (uint32_t)__cvta_generic_to_shared(sm);

    const int lane = tid & 31, warp = tid >> 5;
    const int g = lane >> 2, tg = lane & 3;
    const int wm = warp >> 2, wn = warp & 3;

    int acc1[2][4][4], acc23[2][4][4];
#pragma unroll
    for (int mi = 0; mi < 2; ++mi)
#pragma unroll
        for (int ni = 0; ni < 4; ++ni)
#pragma unroll
            for (int q = 0; q < 4; ++q) { acc1[mi][ni][q] = 0; acc23[mi][ni][q] = 0; }

    constexpr int KT = I_ / BK;   // 32
    load_stage(smu, 0, aH, aL, bH, bL, 0, r, cc);
    cp_commit();
    for (int kt = 0; kt < KT; ++kt) {
        cp_wait<0>();
        __syncthreads();
        if (kt + 1 < KT) {
            load_stage(smu, (kt + 1) & 1, aH, aL, bH, bL, (kt + 1) * BK, r, cc);
            cp_commit();
        }
        compute_stage(sm + (size_t)(kt & 1) * STAGE, g, tg, wm, wn, acc1, acc23);
    }

    // epilogue: dequant (S_H * per-channel), bias, gate scale, scatter-add
    const float* bp = b_proj + e * H_;
#pragma unroll
    for (int mi = 0; mi < 2; ++mi) {
        const int rr = wm * 32 + mi * 16 + g;
#pragma unroll
        for (int ni = 0; ni < 4; ++ni) {
            const int colg = n0 + wn * 32 + ni * 8 + 2 * tg;
            const float sc0 = S_H * __ldg(&g_spj[e * H_ + colg]);
            const float sc1 = S_H * __ldg(&g_spj[e * H_ + colg + 1]);
            if (rr < rem) {
                const int tk = tok_s[rr];
                const float gv = gate_s[rr];
                const float v0 = (16384.f * (float)acc1[mi][ni][0] +
                                  128.f * (float)acc23[mi][ni][0]) * sc0 + bp[colg];
                const float v1 = (16384.f * (float)acc1[mi][ni][1] +
                                  128.f * (float)acc23[mi][ni][1]) * sc1 + bp[colg + 1];
                atomicAdd(out + (size_t)tk * H_ + colg,     gv * v0);
                atomicAdd(out + (size_t)tk * H_ + colg + 1, gv * v1);
            }
            if (rr + 8 < rem) {
                const int tk = tok_s[rr + 8];
                const float gv = gate_s[rr + 8];
                const float v0 = (16384.f * (float)acc1[mi][ni][2] +
                                  128.f * (float)acc23[mi][ni][2]) * sc0 + bp[colg];
                const float v1 = (16384.f * (float)acc1[mi][ni][3] +
                                  128.f * (float)acc23[mi][ni][3]) * sc1 + bp[colg + 1];
                atomicAdd(out + (size_t)tk * H_ + colg,     gv * v0);
                atomicAdd(out + (size_t)tk * H_ + colg + 1, gv * v1);
            }
        }
    }
}

// ---------------- launch ----------------
extern "C" void kernel_launch(void* const* d_in, const int* in_sizes, int n_in,
                              void* d_out, int out_size) {
    const float* x      = (const float*)d_in[0];
    const float* w_gate = (const float*)d_in[1];
    const float* w_fc   = (const float*)d_in[2];
    const float* b_fc   = (const float*)d_in[3];
    const float* w_proj = (const float*)d_in[4];
    const float* b_proj = (const float*)d_in[5];
    float* out = (float*)d_out;

    cudaFuncSetAttribute(gemm_fc_kernel,   cudaFuncAttributeMaxDynamicSharedMemorySize, SMEM_TOTAL);
    cudaFuncSetAttribute(gemm_proj_kernel, cudaFuncAttributeMaxDynamicSharedMemorySize, SMEM_TOTAL);

    constexpr int QBLOCKS = T_ + E_ * I_ + E_ * H_;   // 40960 rows

    // launch order: quant(0) route(1) scan(2) gemm_fc(3) gemm_proj(4)
    // -> ncu's fixed capture slot (launch index 3) lands on gemm_fc_kernel.
    quant_all_kernel<<<QBLOCKS, 128>>>((const float4*)x, (const float4*)w_fc,
                                       (const float4*)w_proj, (float4*)out);
    route_kernel<<<T_ / 128, 128>>>(x, w_gate);
    scan_kernel<<<1, 1>>>();
    gemm_fc_kernel<<<dim3(I_ / BN, T_ / BM, E_), 512, SMEM_TOTAL>>>(b_fc);
    gemm_proj_kernel<<<dim3(H_ / BN, T_ / BM, E_), 512, SMEM_TOTAL>>>(b_proj, out);
}

// round 17
// speedup vs baseline: 4.1017x; 4.1017x over previous
// MoE top-2, grouped-GEMM formulation for GB300 (sm_103a).
// Round 16: revert int8 (s8 MMA is 4-5x slower per instr on the fallback path;
//           R16 measured 6231us @ tensor=85.8%). Base = R15 fp16 (1857.7us).
//           Change: GEMM2 goes 1-term — hmid stored as a SINGLE fp16 plane
//           (quant err ~2e-4 source), GEMM2 computes ah*bh only.
//           Calibrated linear error model: sources B1+B2+hmid = ~6e-4 < 1e-3.
//           MMA equiv 2.0 -> 1.5.
//   kS: merged zero(out,counts) + split x (hi/lo) + w_fc/w_proj (hi only)
//   k1: router   k2: scan
//   k3: grouped GEMM1  hmid = gelu(x @ w_fc^T + b_fc)   [2-term fp16 mma]
//   k4: grouped GEMM2  out += gate * (hmid @ w_proj^T + b_proj) [1-term fp16 mma]
#include <cuda_runtime.h>
#include <cuda_fp16.h>
#include <cstdint>

#define DEVFN __device__ __forceinline__

constexpr int H_ = 1024;
constexpr int I_ = 2048;
constexpr int E_ = 8;
constexpr int T_ = 16384;
constexpr int NPAIR = 2 * T_;

constexpr int BM = 128, BN = 128, BK = 32;
constexpr int PB = 40;                          // fp16 elems per smem row (80 B pitch)
constexpr int PLANE_BYTES = BM * PB * 2;        // 10240 B
constexpr int STAGE1 = 3 * PLANE_BYTES;         // GEMM1: Ahi, Alo, Bhi
constexpr int STAGE2 = 2 * PLANE_BYTES;         // GEMM2: Ahi, Bhi
constexpr int SMEM1 = 2 * STAGE1;               // 61440 B
constexpr int SMEM2 = 2 * STAGE2;               // 40960 B

// ---------------- scratch (device globals; no runtime allocation) ----------------
__device__ int   g_counts[E_];
__device__ int   g_offsets[E_];
__device__ int   g_tok[E_ * T_];
__device__ float g_gate[E_ * T_];

__device__ __half g_xhi[T_ * H_],        g_xlo[T_ * H_];
__device__ __half g_wfchi[E_ * I_ * H_];
__device__ __half g_wprojhi[E_ * H_ * I_];
__device__ __half g_hmhi[(long long)NPAIR * I_];   // single plane

// ---------------- small helpers ----------------
DEVFN void cp_async16(uint32_t smem_addr, const void* gptr) {
    asm volatile("cp.async.cg.shared.global [%0], [%1], 16;\n"
                 :: "r"(smem_addr), "l"(gptr));
}
DEVFN void cp_commit() { asm volatile("cp.async.commit_group;\n"); }
template <int N> DEVFN void cp_wait() {
    asm volatile("cp.async.wait_group %0;\n" :: "n"(N));
}

DEVFN void mma_f16(float c[4], const uint32_t a[4], uint32_t b0, uint32_t b1) {
    asm volatile(
        "mma.sync.aligned.m16n8k16.row.col.f32.f16.f16.f32 "
        "{%0,%1,%2,%3}, {%4,%5,%6,%7}, {%8,%9}, {%0,%1,%2,%3};\n"
        : "+f"(c[0]), "+f"(c[1]), "+f"(c[2]), "+f"(c[3])
        : "r"(a[0]), "r"(a[1]), "r"(a[2]), "r"(a[3]), "r"(b0), "r"(b1));
}

DEVFN float gelu_f(float v) {
    return 0.5f * v * (1.0f + erff(v * 0.70710678118654752440f));
}

DEVFN uint32_t pack2h(__half a, __half b) {
    return (uint32_t)__half_as_ushort(a) | ((uint32_t)__half_as_ushort(b) << 16);
}
DEVFN void split2h(float v0, float v1, uint32_t& hi, uint32_t& lo) {
    const __half h0 = __float2half_rn(v0);
    const __half h1 = __float2half_rn(v1);
    const __half l0 = __float2half_rn(v0 - __half2float(h0));
    const __half l1 = __float2half_rn(v1 - __half2float(h1));
    hi = pack2h(h0, h1);
    lo = pack2h(l0, l1);
}
DEVFN uint32_t hi2h(float v0, float v1) {
    return pack2h(__float2half_rn(v0), __float2half_rn(v1));
}

// ---- GEMM1 per-stage compute: 2-term (ah*bh + al*bh), warp tile 64x32 ----
DEVFN void compute_stage2t(const __half* __restrict__ Ah, const __half* __restrict__ Al,
                           const __half* __restrict__ Bh,
                           int g, int tg, int wm, int wn, float acc[4][4][4]) {
#pragma unroll
    for (int ks = 0; ks < 2; ++ks) {
        const int kc = ks * 16 + 2 * tg;
        uint32_t ah[4][4], al[4][4];
#pragma unroll
        for (int mi = 0; mi < 4; ++mi) {
            const int o = (wm * 64 + mi * 16 + g) * PB + kc;
            ah[mi][0] = *(const uint32_t*)(Ah + o);
            ah[mi][1] = *(const uint32_t*)(Ah + o + 8 * PB);
            ah[mi][2] = *(const uint32_t*)(Ah + o + 8);
            ah[mi][3] = *(const uint32_t*)(Ah + o + 8 * PB + 8);
            al[mi][0] = *(const uint32_t*)(Al + o);
            al[mi][1] = *(const uint32_t*)(Al + o + 8 * PB);
            al[mi][2] = *(const uint32_t*)(Al + o + 8);
            al[mi][3] = *(const uint32_t*)(Al + o + 8 * PB + 8);
        }
#pragma unroll
        for (int ni = 0; ni < 4; ++ni) {
            const int o = (wn * 32 + ni * 8 + g) * PB + kc;
            const uint32_t bh0 = *(const uint32_t*)(Bh + o);
            const uint32_t bh1 = *(const uint32_t*)(Bh + o + 8);
#pragma unroll
            for (int mi = 0; mi < 4; ++mi)
                mma_f16(acc[mi][ni], ah[mi], bh0, bh1);
#pragma unroll
            for (int mi = 0; mi < 4; ++mi)
                mma_f16(acc[mi][ni], al[mi], bh0, bh1);
        }
    }
}

// ---- GEMM2 per-stage compute: 1-term (ah*bh) ----
DEVFN void compute_stage1t(const __half* __restrict__ Ah, const __half* __restrict__ Bh,
                           int g, int tg, int wm, int wn, float acc[4][4][4]) {
#pragma unroll
    for (int ks = 0; ks < 2; ++ks) {
        const int kc = ks * 16 + 2 * tg;
        uint32_t ah[4][4];
#pragma unroll
        for (int mi = 0; mi < 4; ++mi) {
            const int o = (wm * 64 + mi * 16 + g) * PB + kc;
            ah[mi][0] = *(const uint32_t*)(Ah + o);
            ah[mi][1] = *(const uint32_t*)(Ah + o + 8 * PB);
            ah[mi][2] = *(const uint32_t*)(Ah + o + 8);
            ah[mi][3] = *(const uint32_t*)(Ah + o + 8 * PB + 8);
        }
#pragma unroll
        for (int ni = 0; ni < 4; ++ni) {
            const int o = (wn * 32 + ni * 8 + g) * PB + kc;
            const uint32_t bh0 = *(const uint32_t*)(Bh + o);
            const uint32_t bh1 = *(const uint32_t*)(Bh + o + 8);
#pragma unroll
            for (int mi = 0; mi < 4; ++mi)
                mma_f16(acc[mi][ni], ah[mi], bh0, bh1);
        }
    }
}

// stage loaders
DEVFN void load_tiles3(uint32_t smu, int stage,
                       const __half* const aHi[2], const __half* const aLo[2],
                       const __half* const bHi[2], int k0, int r, int cc) {
    const uint32_t sb = smu + (uint32_t)(stage * STAGE1);
#pragma unroll
    for (int p = 0; p < 2; ++p) {
        const uint32_t so = (uint32_t)((r + p * 64) * 80 + cc * 16);
        cp_async16(sb + so, aHi[p] + k0);
        cp_async16(sb + PLANE_BYTES + so, aLo[p] + k0);
        cp_async16(sb + 2 * PLANE_BYTES + so, bHi[p] + k0);
    }
}
DEVFN void load_tiles2(uint32_t smu, int stage,
                       const __half* const aHi[2], const __half* const bHi[2],
                       int k0, int r, int cc) {
    const uint32_t sb = smu + (uint32_t)(stage * STAGE2);
#pragma unroll
    for (int p = 0; p < 2; ++p) {
        const uint32_t so = (uint32_t)((r + p * 64) * 80 + cc * 16);
        cp_async16(sb + so, aHi[p] + k0);
        cp_async16(sb + PLANE_BYTES + so, bHi[p] + k0);
    }
}

// ---------------- kS: merged zero + split ----------------
__global__ void split_all_kernel(const float4* __restrict__ x,
                                 const float4* __restrict__ wfc,
                                 const float4* __restrict__ wproj,
                                 uint2* __restrict__ xhi, uint2* __restrict__ xlo,
                                 uint2* __restrict__ fchi, uint2* __restrict__ pjhi,
                                 float4* __restrict__ out) {
    constexpr size_t N1 = (size_t)T_ * H_ / 4;
    constexpr size_t N2 = (size_t)E_ * I_ * H_ / 4;
    size_t i = (size_t)blockIdx.x * 256 + threadIdx.x;
    if (blockIdx.x == 0 && threadIdx.x < E_) g_counts[threadIdx.x] = 0;
    if (i < N1) {
        out[i] = make_float4(0.f, 0.f, 0.f, 0.f);
        const float4 v = x[i];
        uint2 h, l;
        split2h(v.x, v.y, h.x, l.x);
        split2h(v.z, v.w, h.y, l.y);
        xhi[i] = h;
        xlo[i] = l;
    } else {
        uint2* hi;
        const float4* in;
        if (i < N1 + N2) { i -= N1;      in = wfc;   hi = fchi; }
        else             { i -= N1 + N2; in = wproj; hi = pjhi; }
        const float4 v = in[i];
        hi[i] = make_uint2(hi2h(v.x, v.y), hi2h(v.z, v.w));
    }
}

// ---------------- k1: router ----------------
__global__ void route_kernel(const float* __restrict__ x,
                             const float* __restrict__ w_gate) {
    __shared__ float4 sWg[E_ * (H_ / 4)];   // 32 KB
    const int tid = threadIdx.x;
    for (int i = tid; i < E_ * (H_ / 4); i += 128)
        sWg[i] = ((const float4*)w_gate)[i];
    __syncthreads();

    const int t = blockIdx.x * 128 + tid;
    const float4* xr = (const float4*)(x + (size_t)t * H_);
    float acc[E_];
#pragma unroll
    for (int e = 0; e < E_; ++e) acc[e] = 0.f;

    for (int i = 0; i < H_ / 4; ++i) {
        const float4 v = xr[i];
#pragma unroll
        for (int e = 0; e < E_; ++e) {
            const float4 w = sWg[e * (H_ / 4) + i];
            acc[e] = fmaf(v.x, w.x, fmaf(v.y, w.y, fmaf(v.z, w.z, fmaf(v.w, w.w, acc[e]))));
        }
    }

    int e1 = 0; float v1 = acc[0];
#pragma unroll
    for (int e = 1; e < E_; ++e) if (acc[e] > v1) { v1 = acc[e]; e1 = e; }
    int e2 = -1; float v2 = -3.4e38f;
#pragma unroll
    for (int e = 0; e < E_; ++e) if (e != e1 && acc[e] > v2) { v2 = acc[e]; e2 = e; }

    const float d  = expf(v2 - v1);
    const float iv = 1.0f / (1.0f + d);
    const float g1 = iv, g2 = d * iv;

    int p1 = atomicAdd(&g_counts[e1], 1);
    g_tok[e1 * T_ + p1] = t;  g_gate[e1 * T_ + p1] = g1;
    int p2 = atomicAdd(&g_counts[e2], 1);
    g_tok[e2 * T_ + p2] = t;  g_gate[e2 * T_ + p2] = g2;
}

// ---------------- k2: exclusive scan ----------------
__global__ void scan_kernel() {
    int o = 0;
#pragma unroll
    for (int e = 0; e < E_; ++e) { g_offsets[e] = o; o += g_counts[e]; }
}

// ---------------- k3: grouped GEMM1 (2-term fp16) ----------------
__global__ __launch_bounds__(256, 2)
void gemm_fc_kernel(const float* __restrict__ b_fc) {
    const int e    = blockIdx.z;
    const int tile = blockIdx.y;
    const int cnt  = g_counts[e];
    if (tile * BM >= cnt) return;
    const int rem  = min(cnt - tile * BM, BM);
    const int hoff = g_offsets[e];
    const int n0   = blockIdx.x * BN;

    extern __shared__ __half sm[];
    __shared__ int tok_s[BM];

    const int tid = threadIdx.x;
    if (tid < BM) {
        const int rr = tile * BM + tid;
        tok_s[tid] = g_tok[e * T_ + min(rr, cnt - 1)];
    }
    __syncthreads();

    const int cc = tid & 3;
    const int r  = tid >> 2;
    const __half* aHi[2]; const __half* aLo[2]; const __half* bHi[2];
#pragma unroll
    for (int p = 0; p < 2; ++p) {
        const int row = r + p * 64;
        const size_t ao = (size_t)tok_s[row] * H_ + cc * 8;
        const size_t bo = ((size_t)e * I_ + n0 + row) * H_ + cc * 8;
        aHi[p] = g_xhi + ao;    aLo[p] = g_xlo + ao;
        bHi[p] = g_wfchi + bo;
    }
    const uint32_t smu = (uint32_t)__cvta_generic_to_shared(sm);

    const int lane = tid & 31, warp = tid >> 5;
    const int g = lane >> 2, tg = lane & 3;
    const int wm = warp >> 2, wn = warp & 3;

    float acc[4][4][4];
#pragma unroll
    for (int mi = 0; mi < 4; ++mi)
#pragma unroll
        for (int ni = 0; ni < 4; ++ni)
#pragma unroll
            for (int q = 0; q < 4; ++q) acc[mi][ni][q] = 0.f;

    constexpr int KT = H_ / BK;   // 32
    load_tiles3(smu, 0, aHi, aLo, bHi, 0, r, cc);
    cp_commit();
    for (int kt = 0; kt < KT; ++kt) {
        cp_wait<0>();
        __syncthreads();
        if (kt + 1 < KT) {
            load_tiles3(smu, (kt + 1) & 1, aHi, aLo, bHi, (kt + 1) * BK, r, cc);
            cp_commit();
        }
        const __half* st = sm + (size_t)(kt & 1) * (STAGE1 / 2);
        compute_stage2t(st, st + PLANE_BYTES / 2, st + PLANE_BYTES, g, tg, wm, wn, acc);
    }

    // epilogue: bias + gelu, store hmid as single fp16 plane
    const float* bf = b_fc + e * I_;
    const size_t base = (size_t)(hoff + tile * BM);
#pragma unroll
    for (int mi = 0; mi < 4; ++mi) {
        const int rr = wm * 64 + mi * 16 + g;
#pragma unroll
        for (int ni = 0; ni < 4; ++ni) {
            const int colg = n0 + wn * 32 + ni * 8 + 2 * tg;
            if (rr < rem) {
                const size_t o = (base + rr) * I_ + colg;
                *(uint32_t*)(g_hmhi + o) =
                    hi2h(gelu_f(acc[mi][ni][0] + bf[colg]),
                         gelu_f(acc[mi][ni][1] + bf[colg + 1]));
            }
            if (rr + 8 < rem) {
                const size_t o = (base + rr + 8) * I_ + colg;
                *(uint32_t*)(g_hmhi + o) =
                    hi2h(gelu_f(acc[mi][ni][2] + bf[colg]),
                         gelu_f(acc[mi][ni][3] + bf[colg + 1]));
            }
        }
    }
}

// ---------------- k4: grouped GEMM2 (1-term fp16) ----------------
__global__ __launch_bounds__(256, 2)
void gemm_proj_kernel(const float* __restrict__ b_proj, float* __restrict__ out) {
    const int e    = blockIdx.z;
    const int tile = blockIdx.y;
    const int cnt  = g_counts[e];
    if (tile * BM >= cnt) return;
    const int rem  = min(cnt - tile * BM, BM);
    const int hoff = g_offsets[e];
    const int n0   = blockIdx.x * BN;

    extern __shared__ __half sm[];
    __shared__ int   tok_s[BM];
    __shared__ float gate_s[BM];

    const int tid = threadIdx.x;
    if (tid < BM) {
        const int rr  = tile * BM + tid;
        const int idx = e * T_ + min(rr, cnt - 1);
        tok_s[tid]  = g_tok[idx];
        gate_s[tid] = g_gate[idx];
    }
    __syncthreads();

    const int cc = tid & 3;
    const int r  = tid >> 2;
    const __half* aHi[2]; const __half* bHi[2];
#pragma unroll
    for (int p = 0; p < 2; ++p) {
        const int row  = r + p * 64;
        const int slot = min(hoff + tile * BM + row, NPAIR - 1);
        aHi[p] = g_hmhi + (size_t)slot * I_ + cc * 8;
        bHi[p] = g_wprojhi + ((size_t)e * H_ + n0 + row) * I_ + cc * 8;
    }
    const uint32_t smu = (uint32_t)__cvta_generic_to_shared(sm);

    const int lane = tid & 31, warp = tid >> 5;
    const int g = lane >> 2, tg = lane & 3;
    const int wm = warp >> 2, wn = warp & 3;

    float acc[4][4][4];
#pragma unroll
    for (int mi = 0; mi < 4; ++mi)
#pragma unroll
        for (int ni = 0; ni < 4; ++ni)
#pragma unroll
            for (int q = 0; q < 4; ++q) acc[mi][ni][q] = 0.f;

    constexpr int KT = I_ / BK;   // 64
    load_tiles2(smu, 0, aHi, bHi, 0, r, cc);
    cp_commit();
    for (int kt = 0; kt < KT; ++kt) {
        cp_wait<0>();
        __syncthreads();
        if (kt + 1 < KT) {
            load_tiles2(smu, (kt + 1) & 1, aHi, bHi, (kt + 1) * BK, r, cc);
            cp_commit();
        }
        const __half* st = sm + (size_t)(kt & 1) * (STAGE2 / 2);
        compute_stage1t(st, st + PLANE_BYTES / 2, g, tg, wm, wn, acc);
    }

    // epilogue: bias, gate scale, scatter-add
    const float* bp = b_proj + e * H_;
#pragma unroll
    for (int mi = 0; mi < 4; ++mi) {
        const int rr = wm * 64 + mi * 16 + g;
#pragma unroll
        for (int ni = 0; ni < 4; ++ni) {
            const int colg = n0 + wn * 32 + ni * 8 + 2 * tg;
            if (rr < rem) {
                const int tk = tok_s[rr];
                const float gv = gate_s[rr];
                atomicAdd(out + (size_t)tk * H_ + colg,     gv * (acc[mi][ni][0] + bp[colg]));
                atomicAdd(out + (size_t)tk * H_ + colg + 1, gv * (acc[mi][ni][1] + bp[colg + 1]));
            }
            if (rr + 8 < rem) {
                const int tk = tok_s[rr + 8];
                const float gv = gate_s[rr + 8];
                atomicAdd(out + (size_t)tk * H_ + colg,     gv * (acc[mi][ni][2] + bp[colg]));
                atomicAdd(out + (size_t)tk * H_ + colg + 1, gv * (acc[mi][ni][3] + bp[colg + 1]));
            }
        }
    }
}

// ---------------- launch ----------------
extern "C" void kernel_launch(void* const* d_in, const int* in_sizes, int n_in,
                              void* d_out, int out_size) {
    const float* x      = (const float*)d_in[0];
    const float* w_gate = (const float*)d_in[1];
    const float* w_fc   = (const float*)d_in[2];
    const float* b_fc   = (const float*)d_in[3];
    const float* w_proj = (const float*)d_in[4];
    const float* b_proj = (const float*)d_in[5];
    float* out = (float*)d_out;

    cudaFuncSetAttribute(gemm_fc_kernel,   cudaFuncAttributeMaxDynamicSharedMemorySize, SMEM1);
    cudaFuncSetAttribute(gemm_proj_kernel, cudaFuncAttributeMaxDynamicSharedMemorySize, SMEM2);

    static uint2* p_xhi = nullptr;
    static uint2* p_xlo, *p_wfchi, *p_wprojhi;
    if (!p_xhi) {
        void* p;
        cudaGetSymbolAddress(&p, g_xhi);     p_xhi     = (uint2*)p;
        cudaGetSymbolAddress(&p, g_xlo);     p_xlo     = (uint2*)p;
        cudaGetSymbolAddress(&p, g_wfchi);   p_wfchi   = (uint2*)p;
        cudaGetSymbolAddress(&p, g_wprojhi); p_wprojhi = (uint2*)p;
    }

    constexpr int SPLIT_BLOCKS = (T_ * H_ + E_ * I_ * H_ + E_ * H_ * I_) / (4 * 256);

    // launch order: split_all(0) route(1) scan(2) gemm_fc(3) gemm_proj(4)
    split_all_kernel<<<SPLIT_BLOCKS, 256>>>((const float4*)x, (const float4*)w_fc,
                                            (const float4*)w_proj,
                                            p_xhi, p_xlo, p_wfchi, p_wprojhi,
                                            (float4*)out);
    route_kernel<<<T_ / 128, 128>>>(x, w_gate);
    scan_kernel<<<1, 1>>>();
    gemm_fc_kernel<<<dim3(I_ / BN, T_ / BM, E_), 256, SMEM1>>>(b_fc);
    gemm_proj_kernel<<<dim3(H_ / BN, T_ / BM, E_), 256, SMEM2>>>(b_proj, out);
}